// round 2
// baseline (speedup 1.0000x reference)
#include <cuda_runtime.h>

#define NPOS 65536
#define NPOSf 65536.0f
typedef unsigned long long u64;

// persistent scratch (device globals: no allocation anywhere)
__device__ float g_x[32 * NPOS];          // residual stream
__device__ float g_r[32 * NPOS];          // pre-BN layer output
__device__ float g_z[128 * NPOS];         // end_conv1 output
__device__ float g_stats[42][2][128];     // [op][sum|sumsq][channel]

__device__ __forceinline__ float mishf(float v) {
    // mish(v) = v * u(u+2)/(u(u+2)+2), u = e^v  (clamped; exact tanh(softplus))
    float u = __expf(fminf(v, 20.0f));
    float w = fmaf(u, u, u + u);
    return v * __fdividef(w, w + 2.0f);
}

__device__ __forceinline__ void fma2(u64 &d, u64 a, u64 b, u64 c) {
    asm("fma.rn.f32x2 %0, %1, %2, %3;" : "=l"(d) : "l"(a), "l"(b), "l"(c));
}
__device__ __forceinline__ u64 pack2(float f) {
    u64 r; unsigned b = __float_as_uint(f);
    asm("mov.b64 %0, {%1, %1};" : "=l"(r) : "r"(b));
    return r;
}

// block-wide per-channel reduction of vals[32] (optionally squared) over 256
// threads; float atomicAdd of the block partial into gout[c].
__device__ __forceinline__ void block_reduce32(float* red, float* part,
                                               const float* vals, int tid,
                                               float* gout, bool sq) {
    __syncthreads();
    #pragma unroll
    for (int c = 0; c < 32; c++) {
        float v = vals[c];
        red[tid * 33 + c] = sq ? v * v : v;
    }
    __syncthreads();
    {
        int c = tid & 31, seg = tid >> 5;
        int base = seg * 32;
        float s = 0.f;
        #pragma unroll 8
        for (int t = 0; t < 32; t++) s += red[(base + t) * 33 + c];
        part[seg * 32 + c] = s;
    }
    __syncthreads();
    if (tid < 32) {
        float tot = 0.f;
        #pragma unroll
        for (int s = 0; s < 8; s++) tot += part[s * 32 + tid];
        atomicAdd(gout + tid, tot);
    }
}

// gate conv (16x32) -> concat-mish -> res conv (32x32)
__device__ __forceinline__ void gate_res(const float* xn, float* rn,
                                         const float* s_gw, const float* s_gb,
                                         const float* s_rw, const float* s_rb) {
    float cm[32];
    const float4* gw4 = (const float4*)s_gw;
    #pragma unroll
    for (int j = 0; j < 16; j++) {
        float a = s_gb[j];
        #pragma unroll
        for (int q = 0; q < 8; q++) {
            float4 w = gw4[j * 8 + q];
            a = fmaf(w.x, xn[q * 4 + 0], a);
            a = fmaf(w.y, xn[q * 4 + 1], a);
            a = fmaf(w.z, xn[q * 4 + 2], a);
            a = fmaf(w.w, xn[q * 4 + 3], a);
        }
        cm[j]      = mishf(a);
        cm[j + 16] = mishf(-a);
    }
    const float4* rw4 = (const float4*)s_rw;
    #pragma unroll
    for (int c = 0; c < 32; c++) {
        float a = s_rb[c];
        #pragma unroll
        for (int q = 0; q < 8; q++) {
            float4 w = rw4[c * 8 + q];
            a = fmaf(w.x, cm[q * 4 + 0], a);
            a = fmaf(w.y, cm[q * 4 + 1], a);
            a = fmaf(w.z, cm[q * 4 + 2], a);
            a = fmaf(w.w, cm[q * 4 + 3], a);
        }
        rn[c] = a;
    }
}

__global__ void k_prep() {
    float* st = &g_stats[0][0][0];
    for (int i = threadIdx.x; i < 42 * 2 * 128; i += blockDim.x) st[i] = 0.f;
}

// start conv (32x256) fused with layer-0 gate/res + stats[0]
__global__ __launch_bounds__(256) void k_start(
    const float* __restrict__ xin,
    const float* __restrict__ start_w, const float* __restrict__ start_b,
    const float* __restrict__ gate_w, const float* __restrict__ gate_b,
    const float* __restrict__ res_w, const float* __restrict__ res_b)
{
    __shared__ __align__(16) float s_red[256 * 33];   // swT alias / reduction
    __shared__ float s_part[256];
    __shared__ __align__(16) float s_gw[512];
    __shared__ __align__(16) float s_rw[1024];
    __shared__ float s_gb[16], s_rb[32], s_sb[32];

    int tid = threadIdx.x;
    int p = blockIdx.x * 256 + tid;

    // swT[k][c] = start_w[c][k]
    for (int idx = tid; idx < 8192; idx += 256) {
        int k = idx >> 5, c = idx & 31;
        s_red[k * 32 + c] = start_w[c * 256 + k];
    }
    for (int i = tid; i < 512; i += 256)  s_gw[i] = gate_w[i];
    for (int i = tid; i < 1024; i += 256) s_rw[i] = res_w[i];
    if (tid < 16) s_gb[tid] = gate_b[tid];
    if (tid >= 32 && tid < 64) s_rb[tid - 32] = res_b[tid - 32];
    if (tid >= 64 && tid < 96) s_sb[tid - 64] = start_b[tid - 64];
    __syncthreads();

    float acc[32];
    #pragma unroll
    for (int c = 0; c < 32; c++) acc[c] = s_sb[c];
    const float* xp = xin + (size_t)(p & 7) * (256 * 8192) + (p >> 3);
    const float4* swT4 = (const float4*)s_red;
    #pragma unroll 4
    for (int k = 0; k < 256; k++) {
        float xv = xp[k * 8192];
        #pragma unroll
        for (int q = 0; q < 8; q++) {
            float4 w = swT4[k * 8 + q];
            acc[q * 4 + 0] = fmaf(w.x, xv, acc[q * 4 + 0]);
            acc[q * 4 + 1] = fmaf(w.y, xv, acc[q * 4 + 1]);
            acc[q * 4 + 2] = fmaf(w.z, xv, acc[q * 4 + 2]);
            acc[q * 4 + 3] = fmaf(w.w, xv, acc[q * 4 + 3]);
        }
    }
    #pragma unroll
    for (int c = 0; c < 32; c++) g_x[c * NPOS + p] = acc[c];

    float rn[32];
    gate_res(acc, rn, s_gw, s_gb, s_rw, s_rb);
    #pragma unroll
    for (int c = 0; c < 32; c++) g_r[c * NPOS + p] = rn[c];

    block_reduce32(s_red, s_part, rn, tid, g_stats[0][0], false);
    block_reduce32(s_red, s_part, rn, tid, g_stats[0][1], true);
}

// apply BN(layer-1) + residual, then gate/res of `layer`, stats[layer]
__global__ __launch_bounds__(256) void k_layer(
    const float* __restrict__ gate_w, const float* __restrict__ gate_b,
    const float* __restrict__ res_w, const float* __restrict__ res_b,
    const float* __restrict__ bn_g, const float* __restrict__ bn_b,
    int layer)
{
    __shared__ __align__(16) float s_red[256 * 33];
    __shared__ float s_part[256];
    __shared__ __align__(16) float s_gw[512];
    __shared__ __align__(16) float s_rw[1024];
    __shared__ float s_gb[16], s_rb[32], s_scale[32], s_shift[32];

    int tid = threadIdx.x;
    int p = blockIdx.x * 256 + tid;

    for (int i = tid; i < 512; i += 256)  s_gw[i] = gate_w[layer * 512 + i];
    for (int i = tid; i < 1024; i += 256) s_rw[i] = res_w[layer * 1024 + i];
    if (tid < 16) s_gb[tid] = gate_b[layer * 16 + tid];
    if (tid >= 32 && tid < 64) s_rb[tid - 32] = res_b[layer * 32 + tid - 32];
    if (tid >= 64 && tid < 96) {
        int c = tid - 64, lp = layer - 1;
        float s = g_stats[lp][0][c], q = g_stats[lp][1][c];
        float m = s * (1.0f / NPOSf);
        float var = q * (1.0f / NPOSf) - m * m;
        float inv = rsqrtf(var + 1e-5f);
        float sc = bn_g[lp * 32 + c] * inv;
        s_scale[c] = sc;
        s_shift[c] = bn_b[lp * 32 + c] - m * sc;
    }
    __syncthreads();

    float xn[32];
    #pragma unroll
    for (int c = 0; c < 32; c++) {
        float xv = g_x[c * NPOS + p];
        float rv = g_r[c * NPOS + p];
        float v = fmaf(s_scale[c], rv, xv + s_shift[c]);
        xn[c] = v;
        g_x[c * NPOS + p] = v;
    }
    float rn[32];
    gate_res(xn, rn, s_gw, s_gb, s_rw, s_rb);
    #pragma unroll
    for (int c = 0; c < 32; c++) g_r[c * NPOS + p] = rn[c];

    block_reduce32(s_red, s_part, rn, tid, g_stats[layer][0], false);
    block_reduce32(s_red, s_part, rn, tid, g_stats[layer][1], true);
}

// apply BN(39) + residual -> final x, stats[40] of x
__global__ __launch_bounds__(256) void k_endA(
    const float* __restrict__ bn_g, const float* __restrict__ bn_b)
{
    __shared__ __align__(16) float s_red[256 * 33];
    __shared__ float s_part[256];
    __shared__ float s_scale[32], s_shift[32];
    int tid = threadIdx.x;
    int p = blockIdx.x * 256 + tid;
    if (tid < 32) {
        int c = tid, lp = 39;
        float s = g_stats[lp][0][c], q = g_stats[lp][1][c];
        float m = s * (1.0f / NPOSf);
        float var = q * (1.0f / NPOSf) - m * m;
        float inv = rsqrtf(var + 1e-5f);
        float sc = bn_g[lp * 32 + c] * inv;
        s_scale[c] = sc;
        s_shift[c] = bn_b[lp * 32 + c] - m * sc;
    }
    __syncthreads();
    float xn[32];
    #pragma unroll
    for (int c = 0; c < 32; c++) {
        float xv = g_x[c * NPOS + p];
        float rv = g_r[c * NPOS + p];
        float v = fmaf(s_scale[c], rv, xv + s_shift[c]);
        xn[c] = v;
        g_x[c * NPOS + p] = v;
    }
    block_reduce32(s_red, s_part, xn, tid, g_stats[40][0], false);
    block_reduce32(s_red, s_part, xn, tid, g_stats[40][1], true);
}

// y = concat_mish(bn1(x)); z = end_conv1(128x64) @ y; stats[41] of z
__global__ __launch_bounds__(256) void k_endB(
    const float* __restrict__ bn1_g, const float* __restrict__ bn1_b,
    const float* __restrict__ w1, const float* __restrict__ b1)
{
    __shared__ __align__(16) float s_red[256 * 33];
    __shared__ float s_part[256];
    __shared__ __align__(16) float s_w[2048];
    __shared__ float s_scale[32], s_shift[32];
    int tid = threadIdx.x;
    int p = blockIdx.x * 256 + tid;
    if (tid < 32) {
        float s = g_stats[40][0][tid], q = g_stats[40][1][tid];
        float m = s * (1.0f / NPOSf);
        float var = q * (1.0f / NPOSf) - m * m;
        float inv = rsqrtf(var + 1e-5f);
        float sc = bn1_g[tid] * inv;
        s_scale[tid] = sc;
        s_shift[tid] = bn1_b[tid] - m * sc;
    }
    __syncthreads();
    float y[64];
    #pragma unroll
    for (int c = 0; c < 32; c++) {
        float t = fmaf(s_scale[c], g_x[c * NPOS + p], s_shift[c]);
        y[c]      = mishf(t);
        y[c + 32] = mishf(-t);
    }
    for (int chunk = 0; chunk < 4; chunk++) {
        __syncthreads();
        for (int i = tid; i < 2048; i += 256) s_w[i] = w1[chunk * 2048 + i];
        __syncthreads();
        float zz[32];
        const float4* w4 = (const float4*)s_w;
        #pragma unroll
        for (int cc = 0; cc < 32; cc++) {
            float a = b1[chunk * 32 + cc];
            #pragma unroll
            for (int q = 0; q < 16; q++) {
                float4 w = w4[cc * 16 + q];
                a = fmaf(w.x, y[q * 4 + 0], a);
                a = fmaf(w.y, y[q * 4 + 1], a);
                a = fmaf(w.z, y[q * 4 + 2], a);
                a = fmaf(w.w, y[q * 4 + 3], a);
            }
            g_z[(chunk * 32 + cc) * NPOS + p] = a;
            zz[cc] = a;
        }
        block_reduce32(s_red, s_part, zz, tid, &g_stats[41][0][chunk * 32], false);
        block_reduce32(s_red, s_part, zz, tid, &g_stats[41][1][chunk * 32], true);
    }
}

// out = end_conv2 (256x256) @ concat_mish(bn2(z)); f32x2 packed FMA.
// block: all 256 out-ch x 64 positions; thread: 8 out-ch x 8 positions.
__global__ __launch_bounds__(256) void k_endC(
    const float* __restrict__ bn2_g, const float* __restrict__ bn2_b,
    const float* __restrict__ w2, const float* __restrict__ b2,
    float* __restrict__ out)
{
    __shared__ __align__(16) float sBuf[256 * 33 + 32 * 64];  // sW | sV, reused as sOut
    __shared__ float sSc[128], sSh[128], sB2[256];
    float* sW = sBuf;                 // [256][33] chunk of W2 (k=32, padded)
    float* sV = sBuf + 256 * 33;      // [32][64]

    int tid = threadIdx.x;
    int ty = tid >> 3;                // 0..31 -> out-ch base ty*8
    int tx = tid & 7;                 // 0..7  -> pos base tx*8
    int p0 = blockIdx.x * 64;
    int l0 = p0 >> 3;

    if (tid < 128) {
        float s = g_stats[41][0][tid], q = g_stats[41][1][tid];
        float m = s * (1.0f / NPOSf);
        float var = q * (1.0f / NPOSf) - m * m;
        float inv = rsqrtf(var + 1e-5f);
        float sc = bn2_g[tid] * inv;
        sSc[tid] = sc;
        sSh[tid] = bn2_b[tid] - m * sc;
    }
    sB2[tid] = b2[tid];

    u64 acc[8][4];
    #pragma unroll
    for (int i = 0; i < 8; i++)
        #pragma unroll
        for (int jp = 0; jp < 4; jp++) acc[i][jp] = 0ULL;

    for (int kc = 0; kc < 8; kc++) {
        __syncthreads();
        // W chunk: sW[o][k] = w2[o*256 + kc*32 + k]
        for (int idx = tid; idx < 8192; idx += 256) {
            int o = idx >> 5, k = idx & 31;
            sW[o * 33 + k] = w2[o * 256 + kc * 32 + k];
        }
        // V chunk: concat_mish(bn2(z))
        for (int idx = tid; idx < 2048; idx += 256) {
            int kk = idx >> 6, qq = idx & 63;
            int c = kc * 32 + kk;
            int zc = (c < 128) ? c : c - 128;
            float t = fmaf(sSc[zc], g_z[zc * NPOS + p0 + qq], sSh[zc]);
            sV[kk * 64 + qq] = mishf((c < 128) ? t : -t);
        }
        __syncthreads();
        int woff = ty * 8 * 33;
        int voff = tx * 8;
        #pragma unroll
        for (int k = 0; k < 32; k++) {
            u64 vv[4];
            #pragma unroll
            for (int jp = 0; jp < 4; jp++)
                vv[jp] = *(const u64*)&sV[k * 64 + voff + jp * 2];
            #pragma unroll
            for (int i = 0; i < 8; i++) {
                u64 wd = pack2(sW[woff + i * 33 + k]);
                #pragma unroll
                for (int jp = 0; jp < 4; jp++)
                    fma2(acc[i][jp], wd, vv[jp], acc[i][jp]);
            }
        }
    }

    // stage + coalesced float4 stores, two halves of out-channels
    for (int oh = 0; oh < 2; oh++) {
        __syncthreads();
        if ((ty >> 4) == oh) {
            int orow = (ty & 15) * 8;
            #pragma unroll
            for (int i = 0; i < 8; i++) {
                float bias = sB2[oh * 128 + orow + i];
                #pragma unroll
                for (int j = 0; j < 8; j++) {
                    int jp = j >> 1;
                    float f = (j & 1) ? __uint_as_float((unsigned)(acc[i][jp] >> 32))
                                      : __uint_as_float((unsigned)acc[i][jp]);
                    // qoff = tx*8 + j  ->  b = j, loff = tx
                    sBuf[(orow + i) * 64 + j * 8 + tx] = f + bias;
                }
            }
        }
        __syncthreads();
        for (int idx = tid; idx < 2048; idx += 256) {
            int oloc = idx >> 4;
            int b = (idx >> 1) & 7;
            int h = idx & 1;
            float4 v = *(float4*)&sBuf[oloc * 64 + b * 8 + h * 4];
            *(float4*)&out[(size_t)b * 2097152 + (size_t)(oh * 128 + oloc) * 8192
                           + l0 + h * 4] = v;
        }
    }
}

extern "C" void kernel_launch(void* const* d_in, const int* in_sizes, int n_in,
                              void* d_out, int out_size) {
    const float* x          = (const float*)d_in[0];
    const float* start_w    = (const float*)d_in[1];
    const float* start_b    = (const float*)d_in[2];
    const float* gate_w     = (const float*)d_in[3];
    const float* gate_b     = (const float*)d_in[4];
    const float* res_w      = (const float*)d_in[5];
    const float* res_b      = (const float*)d_in[6];
    const float* bn_g       = (const float*)d_in[7];
    const float* bn_b       = (const float*)d_in[8];
    const float* end_bn1_g  = (const float*)d_in[9];
    const float* end_bn1_b  = (const float*)d_in[10];
    const float* end_conv1_w = (const float*)d_in[11];
    const float* end_conv1_b = (const float*)d_in[12];
    const float* end_bn2_g  = (const float*)d_in[13];
    const float* end_bn2_b  = (const float*)d_in[14];
    const float* end_conv2_w = (const float*)d_in[15];
    const float* end_conv2_b = (const float*)d_in[16];
    float* out = (float*)d_out;

    k_prep<<<1, 256>>>();
    k_start<<<256, 256>>>(x, start_w, start_b, gate_w, gate_b, res_w, res_b);
    for (int i = 1; i < 40; i++)
        k_layer<<<256, 256>>>(gate_w, gate_b, res_w, res_b, bn_g, bn_b, i);
    k_endA<<<256, 256>>>(bn_g, bn_b);
    k_endB<<<256, 256>>>(end_bn1_g, end_bn1_b, end_conv1_w, end_conv1_b);
    k_endC<<<1024, 256>>>(end_bn2_g, end_bn2_b, end_conv2_w, end_conv2_b, out);
}

// round 3
// speedup vs baseline: 1.0672x; 1.0672x over previous
#include <cuda_runtime.h>

typedef unsigned long long u64;
#define NPOS 65536
#define NPOSf 65536.0f
#define NPART 16

// persistent scratch (device globals)
__device__ float2 g_x2[16 * NPOS];              // residual stream, ch-paired
__device__ float2 g_r2[16 * NPOS];              // pre-BN layer output, ch-paired
__device__ float  g_z[128 * NPOS];              // end_conv1 output
__device__ float  g_statp[NPART][42][2][128];   // partitioned stats

__device__ __forceinline__ float* stat_ptr(int part, int op, int kind) {
    return &g_statp[part][op][kind][0];
}

__device__ __forceinline__ void fma2(u64 &d, u64 a, u64 b, u64 c) {
    asm("fma.rn.f32x2 %0, %1, %2, %3;" : "=l"(d) : "l"(a), "l"(b), "l"(c));
}
__device__ __forceinline__ u64 pack2(float f) {
    u64 r; unsigned b = __float_as_uint(f);
    asm("mov.b64 %0, {%1, %1};" : "=l"(r) : "r"(b));
    return r;
}
__device__ __forceinline__ float lo2(u64 v) { return __uint_as_float((unsigned)v); }
__device__ __forceinline__ float hi2(u64 v) { return __uint_as_float((unsigned)(v >> 32)); }

__device__ __forceinline__ float mishf(float v) {
    float u = __expf(fminf(fmaxf(v, -20.0f), 20.0f));
    float w = fmaf(u, u, u + u);
    return v * __fdividef(w, w + 2.0f);
}

// mish(a) and mish(-a) sharing one exp:
//   u = e^a; tanh(sp(a)) = (u^2+2u)/(u^2+2u+2); tanh(sp(-a)) = (2u+1)/(2u^2+2u+1)
__device__ __forceinline__ void mish_pair(float a, float &mp, float &mn) {
    float ac = fminf(fmaxf(a, -20.0f), 20.0f);
    float u = __expf(ac);
    float A = fmaf(u, u, u + u);
    mp = a * __fdividef(A, A + 2.0f);
    float B = fmaf(2.0f, u, 1.0f);
    mn = -a * __fdividef(B, fmaf(u + u, u, B));
}

// fused single-pass sum/sumsq block reduction of vals[32] over BS threads,
// atomic into stat partition prt, op, channel offset coff.
template<int BS>
__device__ __forceinline__ void reduce_stats(float* red, float* part1, float* part2,
                                             const float* vals, int tid,
                                             int prt, int op, int coff) {
    __syncthreads();
    #pragma unroll
    for (int c = 0; c < 32; c++) red[tid * 34 + c] = vals[c];
    __syncthreads();
    {
        int c = tid & 31, seg = tid >> 5;
        int base = seg * 32;
        float s = 0.f, q = 0.f;
        #pragma unroll
        for (int r = 0; r < 32; r++) {
            float v = red[(base + r) * 34 + c];
            s += v;
            q = fmaf(v, v, q);
        }
        part1[seg * 32 + c] = s;
        part2[seg * 32 + c] = q;
    }
    __syncthreads();
    if (tid < 64) {
        int c = tid & 31, kind = tid >> 5;
        const float* pp = kind ? part2 : part1;
        float t = 0.f;
        #pragma unroll
        for (int sg = 0; sg < BS / 32; sg++) t += pp[sg * 32 + c];
        atomicAdd(stat_ptr(prt, op, kind) + coff + c, t);
    }
}

// combine partitioned stats -> BN scale/shift for 32 channels (threads 0..31)
__device__ __forceinline__ void bn_combine32(const float* g, const float* b, int op,
                                             float* s_scale, float* s_shift, int tid) {
    if (tid < 32) {
        float s = 0.f, q = 0.f;
        #pragma unroll
        for (int pp = 0; pp < NPART; pp++) {
            s += g_statp[pp][op][0][tid];
            q += g_statp[pp][op][1][tid];
        }
        float m = s * (1.0f / NPOSf);
        float var = q * (1.0f / NPOSf) - m * m;
        float inv = rsqrtf(var + 1e-5f);
        float sc = g[tid] * inv;
        s_scale[tid] = sc;
        s_shift[tid] = b[tid] - m * sc;
    }
}

// paired gate(16x32) -> concat-mish -> res(32x32) with f32x2
// s_gw layout [k][j] (j=0..15 contiguous), s_rw layout [k][c] (c contiguous)
__device__ __forceinline__ void gate_res_p(const float* xn, float* rn,
                                           const float* s_gw, const float* s_gb,
                                           const float* s_rw, const float* s_rb) {
    u64 accg[8];
    #pragma unroll
    for (int jp = 0; jp < 8; jp++) accg[jp] = *(const u64*)&s_gb[2 * jp];
    const ulonglong2* gw2 = (const ulonglong2*)s_gw;
    #pragma unroll
    for (int k = 0; k < 32; k++) {
        u64 xk = pack2(xn[k]);
        #pragma unroll
        for (int m = 0; m < 4; m++) {
            ulonglong2 w = gw2[k * 4 + m];
            fma2(accg[2 * m],     w.x, xk, accg[2 * m]);
            fma2(accg[2 * m + 1], w.y, xk, accg[2 * m + 1]);
        }
    }
    float cm[32];
    #pragma unroll
    for (int jp = 0; jp < 8; jp++) {
        float a0 = lo2(accg[jp]), a1 = hi2(accg[jp]);
        mish_pair(a0, cm[2 * jp],     cm[2 * jp + 16]);
        mish_pair(a1, cm[2 * jp + 1], cm[2 * jp + 17]);
    }
    u64 accr[16];
    #pragma unroll
    for (int cp = 0; cp < 16; cp++) accr[cp] = *(const u64*)&s_rb[2 * cp];
    const ulonglong2* rw2 = (const ulonglong2*)s_rw;
    #pragma unroll
    for (int k = 0; k < 32; k++) {
        u64 ck = pack2(cm[k]);
        #pragma unroll
        for (int m = 0; m < 8; m++) {
            ulonglong2 w = rw2[k * 8 + m];
            fma2(accr[2 * m],     w.x, ck, accr[2 * m]);
            fma2(accr[2 * m + 1], w.y, ck, accr[2 * m + 1]);
        }
    }
    #pragma unroll
    for (int cp = 0; cp < 16; cp++) {
        rn[2 * cp]     = lo2(accr[cp]);
        rn[2 * cp + 1] = hi2(accr[cp]);
    }
}

__global__ void k_prep() {
    int idx = blockIdx.x * 512 + threadIdx.x;
    float* st = &g_statp[0][0][0][0];
    if (idx < NPART * 42 * 2 * 128) st[idx] = 0.f;
}

// start conv (32x256) + layer-0 gate/res + stats[0]
__global__ __launch_bounds__(256, 2) void k_start(
    const float* __restrict__ xin,
    const float* __restrict__ start_w, const float* __restrict__ start_b,
    const float* __restrict__ gate_w, const float* __restrict__ gate_b,
    const float* __restrict__ res_w, const float* __restrict__ res_b)
{
    __shared__ __align__(16) float s_red[256 * 34];   // swT alias / reduction
    __shared__ float s_p1[256], s_p2[256];
    __shared__ __align__(16) float s_gw[512];
    __shared__ __align__(16) float s_rw[1024];
    __shared__ __align__(8) float s_gb[16];
    __shared__ __align__(8) float s_rb[32];
    __shared__ __align__(8) float s_sb[32];

    int tid = threadIdx.x;
    int p = blockIdx.x * 256 + tid;
    int prt = blockIdx.x & (NPART - 1);

    // swT[k][c] = start_w[c][k]  (c contiguous -> output pairs)
    for (int idx = tid; idx < 8192; idx += 256) {
        int k = idx >> 5, c = idx & 31;
        s_red[k * 32 + c] = start_w[c * 256 + k];
    }
    for (int i = tid; i < 512; i += 256)  { int j = i & 15, k = i >> 4; s_gw[i] = gate_w[j * 32 + k]; }
    for (int i = tid; i < 1024; i += 256) { int c = i & 31, k = i >> 5; s_rw[i] = res_w[c * 32 + k]; }
    if (tid < 16) s_gb[tid] = gate_b[tid];
    if (tid >= 32 && tid < 64) s_rb[tid - 32] = res_b[tid - 32];
    if (tid >= 64 && tid < 96) s_sb[tid - 64] = start_b[tid - 64];
    __syncthreads();

    u64 acc[16];
    #pragma unroll
    for (int cp = 0; cp < 16; cp++) acc[cp] = *(const u64*)&s_sb[2 * cp];
    const float* xp = xin + (size_t)(p & 7) * (256 * 8192) + (p >> 3);
    const ulonglong2* swT2 = (const ulonglong2*)s_red;
    #pragma unroll 4
    for (int k = 0; k < 256; k++) {
        u64 xk = pack2(xp[k * 8192]);
        #pragma unroll
        for (int m = 0; m < 8; m++) {
            ulonglong2 w = swT2[k * 8 + m];
            fma2(acc[2 * m],     w.x, xk, acc[2 * m]);
            fma2(acc[2 * m + 1], w.y, xk, acc[2 * m + 1]);
        }
    }
    float xn[32];
    #pragma unroll
    for (int cp = 0; cp < 16; cp++) {
        xn[2 * cp] = lo2(acc[cp]);
        xn[2 * cp + 1] = hi2(acc[cp]);
        g_x2[cp * NPOS + p] = make_float2(xn[2 * cp], xn[2 * cp + 1]);
    }
    float rn[32];
    gate_res_p(xn, rn, s_gw, s_gb, s_rw, s_rb);
    #pragma unroll
    for (int cp = 0; cp < 16; cp++) g_r2[cp * NPOS + p] = make_float2(rn[2 * cp], rn[2 * cp + 1]);

    reduce_stats<256>(s_red, s_p1, s_p2, rn, tid, prt, 0, 0);
}

// apply BN(layer-1) + residual, gate/res of `layer`, stats[layer]
__global__ __launch_bounds__(64) void k_layer(
    const float* __restrict__ gate_w, const float* __restrict__ gate_b,
    const float* __restrict__ res_w, const float* __restrict__ res_b,
    const float* __restrict__ bn_g, const float* __restrict__ bn_b,
    int layer)
{
    __shared__ __align__(16) float s_gw[512];
    __shared__ __align__(16) float s_rw[1024];
    __shared__ __align__(16) float s_red[64 * 34];
    __shared__ float s_p1[64], s_p2[64];
    __shared__ __align__(8) float s_gb[16];
    __shared__ __align__(8) float s_rb[32];
    __shared__ float s_scale[32], s_shift[32];

    int tid = threadIdx.x;
    int p = blockIdx.x * 64 + tid;
    int prt = blockIdx.x & (NPART - 1);

    for (int i = tid; i < 512; i += 64)  { int j = i & 15, k = i >> 4; s_gw[i] = gate_w[layer * 512 + j * 32 + k]; }
    for (int i = tid; i < 1024; i += 64) { int c = i & 31, k = i >> 5; s_rw[i] = res_w[layer * 1024 + c * 32 + k]; }
    if (tid < 16) s_gb[tid] = gate_b[layer * 16 + tid];
    if (tid >= 32) s_rb[tid - 32] = res_b[layer * 32 + tid - 32];
    bn_combine32(bn_g + (layer - 1) * 32, bn_b + (layer - 1) * 32, layer - 1,
                 s_scale, s_shift, tid);
    __syncthreads();

    float xn[32];
    #pragma unroll
    for (int cp = 0; cp < 16; cp++) {
        float2 xv = g_x2[cp * NPOS + p];
        float2 rv = g_r2[cp * NPOS + p];
        float v0 = fmaf(s_scale[2 * cp],     rv.x, xv.x + s_shift[2 * cp]);
        float v1 = fmaf(s_scale[2 * cp + 1], rv.y, xv.y + s_shift[2 * cp + 1]);
        xn[2 * cp] = v0; xn[2 * cp + 1] = v1;
        g_x2[cp * NPOS + p] = make_float2(v0, v1);
    }
    float rn[32];
    gate_res_p(xn, rn, s_gw, s_gb, s_rw, s_rb);
    #pragma unroll
    for (int cp = 0; cp < 16; cp++) g_r2[cp * NPOS + p] = make_float2(rn[2 * cp], rn[2 * cp + 1]);

    reduce_stats<64>(s_red, s_p1, s_p2, rn, tid, prt, layer, 0);
}

// apply BN(39) + residual -> final x; stats[40]
__global__ __launch_bounds__(64) void k_endA(
    const float* __restrict__ bn_g, const float* __restrict__ bn_b)
{
    __shared__ __align__(16) float s_red[64 * 34];
    __shared__ float s_p1[64], s_p2[64];
    __shared__ float s_scale[32], s_shift[32];
    int tid = threadIdx.x;
    int p = blockIdx.x * 64 + tid;
    int prt = blockIdx.x & (NPART - 1);
    bn_combine32(bn_g + 39 * 32, bn_b + 39 * 32, 39, s_scale, s_shift, tid);
    __syncthreads();
    float xn[32];
    #pragma unroll
    for (int cp = 0; cp < 16; cp++) {
        float2 xv = g_x2[cp * NPOS + p];
        float2 rv = g_r2[cp * NPOS + p];
        float v0 = fmaf(s_scale[2 * cp],     rv.x, xv.x + s_shift[2 * cp]);
        float v1 = fmaf(s_scale[2 * cp + 1], rv.y, xv.y + s_shift[2 * cp + 1]);
        xn[2 * cp] = v0; xn[2 * cp + 1] = v1;
        g_x2[cp * NPOS + p] = make_float2(v0, v1);
    }
    reduce_stats<64>(s_red, s_p1, s_p2, xn, tid, prt, 40, 0);
}

// y = concat_mish(bn1(x)); z = end_conv1(128x64) @ y; stats[41]
__global__ __launch_bounds__(256, 2) void k_endB(
    const float* __restrict__ bn1_g, const float* __restrict__ bn1_b,
    const float* __restrict__ w1, const float* __restrict__ b1)
{
    __shared__ __align__(16) float s_red[256 * 34];
    __shared__ float s_p1[256], s_p2[256];
    __shared__ __align__(16) float s_w[2048];
    __shared__ float s_scale[32], s_shift[32];
    __shared__ __align__(8) float s_b1[128];
    int tid = threadIdx.x;
    int p = blockIdx.x * 256 + tid;
    int prt = blockIdx.x & (NPART - 1);
    bn_combine32(bn1_g, bn1_b, 40, s_scale, s_shift, tid);
    if (tid < 128) s_b1[tid] = b1[tid];
    __syncthreads();

    float y[64];
    #pragma unroll
    for (int cp = 0; cp < 16; cp++) {
        float2 xv = g_x2[cp * NPOS + p];
        float t0 = fmaf(s_scale[2 * cp],     xv.x, s_shift[2 * cp]);
        float t1 = fmaf(s_scale[2 * cp + 1], xv.y, s_shift[2 * cp + 1]);
        mish_pair(t0, y[2 * cp],     y[2 * cp + 32]);
        mish_pair(t1, y[2 * cp + 1], y[2 * cp + 33]);
    }
    for (int chunk = 0; chunk < 4; chunk++) {
        __syncthreads();
        // s_w[k][cc] = w1[(chunk*32+cc)][k], cc contiguous
        for (int i = tid; i < 2048; i += 256) {
            int cc = i & 31, k = i >> 5;
            s_w[i] = w1[(chunk * 32 + cc) * 64 + k];
        }
        __syncthreads();
        u64 accz[16];
        #pragma unroll
        for (int cp = 0; cp < 16; cp++) accz[cp] = *(const u64*)&s_b1[chunk * 32 + 2 * cp];
        const ulonglong2* wv2 = (const ulonglong2*)s_w;
        #pragma unroll
        for (int k = 0; k < 64; k++) {
            u64 yk = pack2(y[k]);
            #pragma unroll
            for (int m = 0; m < 8; m++) {
                ulonglong2 w = wv2[k * 8 + m];
                fma2(accz[2 * m],     w.x, yk, accz[2 * m]);
                fma2(accz[2 * m + 1], w.y, yk, accz[2 * m + 1]);
            }
        }
        float zz[32];
        #pragma unroll
        for (int cp = 0; cp < 16; cp++) {
            zz[2 * cp] = lo2(accz[cp]);
            zz[2 * cp + 1] = hi2(accz[cp]);
            g_z[(chunk * 32 + 2 * cp) * NPOS + p] = zz[2 * cp];
            g_z[(chunk * 32 + 2 * cp + 1) * NPOS + p] = zz[2 * cp + 1];
        }
        reduce_stats<256>(s_red, s_p1, s_p2, zz, tid, prt, 41, chunk * 32);
    }
}

// out = end_conv2 (256x256) @ concat_mish(bn2(z)); f32x2 packed FMA.
__global__ __launch_bounds__(256) void k_endC(
    const float* __restrict__ bn2_g, const float* __restrict__ bn2_b,
    const float* __restrict__ w2, const float* __restrict__ b2,
    float* __restrict__ out)
{
    __shared__ __align__(16) float sBuf[256 * 33 + 32 * 64];
    __shared__ float sSc[128], sSh[128], sB2[256];
    float* sW = sBuf;
    float* sV = sBuf + 256 * 33;

    int tid = threadIdx.x;
    int ty = tid >> 3;
    int tx = tid & 7;
    int p0 = blockIdx.x * 64;
    int l0 = p0 >> 3;

    if (tid < 128) {
        float s = 0.f, q = 0.f;
        #pragma unroll
        for (int pp = 0; pp < NPART; pp++) {
            s += g_statp[pp][41][0][tid];
            q += g_statp[pp][41][1][tid];
        }
        float m = s * (1.0f / NPOSf);
        float var = q * (1.0f / NPOSf) - m * m;
        float inv = rsqrtf(var + 1e-5f);
        float sc = bn2_g[tid] * inv;
        sSc[tid] = sc;
        sSh[tid] = bn2_b[tid] - m * sc;
    }
    sB2[tid] = b2[tid];

    u64 acc[8][4];
    #pragma unroll
    for (int i = 0; i < 8; i++)
        #pragma unroll
        for (int jp = 0; jp < 4; jp++) acc[i][jp] = 0ULL;

    for (int kc = 0; kc < 8; kc++) {
        __syncthreads();
        for (int idx = tid; idx < 8192; idx += 256) {
            int o = idx >> 5, k = idx & 31;
            sW[o * 33 + k] = w2[o * 256 + kc * 32 + k];
        }
        for (int idx = tid; idx < 2048; idx += 256) {
            int kk = idx >> 6, qq = idx & 63;
            int c = kc * 32 + kk;
            int zc = (c < 128) ? c : c - 128;
            float t = fmaf(sSc[zc], g_z[zc * NPOS + p0 + qq], sSh[zc]);
            sV[kk * 64 + qq] = mishf((c < 128) ? t : -t);
        }
        __syncthreads();
        int woff = ty * 8 * 33;
        int voff = tx * 8;
        #pragma unroll
        for (int k = 0; k < 32; k++) {
            u64 vv[4];
            #pragma unroll
            for (int jp = 0; jp < 4; jp++)
                vv[jp] = *(const u64*)&sV[k * 64 + voff + jp * 2];
            #pragma unroll
            for (int i = 0; i < 8; i++) {
                u64 wd = pack2(sW[woff + i * 33 + k]);
                #pragma unroll
                for (int jp = 0; jp < 4; jp++)
                    fma2(acc[i][jp], wd, vv[jp], acc[i][jp]);
            }
        }
    }

    for (int oh = 0; oh < 2; oh++) {
        __syncthreads();
        if ((ty >> 4) == oh) {
            int orow = (ty & 15) * 8;
            #pragma unroll
            for (int i = 0; i < 8; i++) {
                float bias = sB2[oh * 128 + orow + i];
                #pragma unroll
                for (int j = 0; j < 8; j++) {
                    int jp = j >> 1;
                    float f = (j & 1) ? hi2(acc[i][jp]) : lo2(acc[i][jp]);
                    sBuf[(orow + i) * 64 + j * 8 + tx] = f + bias;
                }
            }
        }
        __syncthreads();
        for (int idx = tid; idx < 2048; idx += 256) {
            int oloc = idx >> 4;
            int b = (idx >> 1) & 7;
            int h = idx & 1;
            float4 v = *(float4*)&sBuf[oloc * 64 + b * 8 + h * 4];
            *(float4*)&out[(size_t)b * 2097152 + (size_t)(oh * 128 + oloc) * 8192
                           + l0 + h * 4] = v;
        }
    }
}

extern "C" void kernel_launch(void* const* d_in, const int* in_sizes, int n_in,
                              void* d_out, int out_size) {
    const float* x           = (const float*)d_in[0];
    const float* start_w     = (const float*)d_in[1];
    const float* start_b     = (const float*)d_in[2];
    const float* gate_w      = (const float*)d_in[3];
    const float* gate_b      = (const float*)d_in[4];
    const float* res_w       = (const float*)d_in[5];
    const float* res_b       = (const float*)d_in[6];
    const float* bn_g        = (const float*)d_in[7];
    const float* bn_b        = (const float*)d_in[8];
    const float* end_bn1_g   = (const float*)d_in[9];
    const float* end_bn1_b   = (const float*)d_in[10];
    const float* end_conv1_w = (const float*)d_in[11];
    const float* end_conv1_b = (const float*)d_in[12];
    const float* end_bn2_g   = (const float*)d_in[13];
    const float* end_bn2_b   = (const float*)d_in[14];
    const float* end_conv2_w = (const float*)d_in[15];
    const float* end_conv2_b = (const float*)d_in[16];
    float* out = (float*)d_out;

    k_prep<<<336, 512>>>();
    k_start<<<256, 256>>>(x, start_w, start_b, gate_w, gate_b, res_w, res_b);
    for (int i = 1; i < 40; i++)
        k_layer<<<1024, 64>>>(gate_w, gate_b, res_w, res_b, bn_g, bn_b, i);
    k_endA<<<1024, 64>>>(bn_g, bn_b);
    k_endB<<<256, 256>>>(end_bn1_g, end_bn1_b, end_conv1_w, end_conv1_b);
    k_endC<<<1024, 256>>>(end_bn2_g, end_bn2_b, end_conv2_w, end_conv2_b, out);
}